// round 2
// baseline (speedup 1.0000x reference)
#include <cuda_runtime.h>
#include <cstdint>

// DenseRoutingMaskLayer: per-row argmax over 8 routing logits selects a
// contiguous 512-float chunk of the 4096-wide input row.
//   inputs:          [B=16384, D=4096] f32   (d_in[0])
//   routing_inputs:  [B=16384, R=8]    f32   (d_in[1])
//   out:             [B=16384, W=512]  f32
//
// Round 2: 4 rows per warp.
//  - One coalesced 32-lane load fetches 4 rows x 8 logits (128B).
//  - 3-step xor-butterfly argmax within each 8-lane group (min-index
//    tie-break == jnp.argmax first-occurrence semantics).
//  - All 16 LDG.128 issued before any STG.128 -> MLP 16 per warp.
//  - __ldcs/__stcs streaming hints (single-touch data).

constexpr int ROWS_PER_WARP = 4;
constexpr int WARPS_PER_BLOCK = 8;
constexpr int ROWS_PER_BLOCK = ROWS_PER_WARP * WARPS_PER_BLOCK;  // 32

__global__ __launch_bounds__(256, 3)
void dense_routing_mask_kernel(const float* __restrict__ inputs,
                               const float* __restrict__ routing,
                               float* __restrict__ out,
                               int B) {
    const int warp = threadIdx.x >> 5;
    const int lane = threadIdx.x & 31;
    const int row0 = blockIdx.x * ROWS_PER_BLOCK + warp * ROWS_PER_WARP;
    if (row0 >= B) return;

    // ---- routing load: 4 rows x 8 logits = 32 floats, one coalesced load ----
    // lane L holds routing[row0 + L/8][L%8]
    float v  = __ldcs(routing + (size_t)row0 * 8 + lane);
    int   idx = lane & 7;

    // ---- argmax within each 8-lane group (xor butterfly, min-index ties) ----
    #pragma unroll
    for (int off = 1; off < 8; off <<= 1) {
        float v2 = __shfl_xor_sync(0xffffffffu, v,   off);
        int   i2 = __shfl_xor_sync(0xffffffffu, idx, off);
        if (v2 > v || (v2 == v && i2 < idx)) { v = v2; idx = i2; }
    }
    // every lane in group g (lanes 8g..8g+7) now has argmax for row row0+g

    int idxs[ROWS_PER_WARP];
    #pragma unroll
    for (int r = 0; r < ROWS_PER_WARP; r++)
        idxs[r] = __shfl_sync(0xffffffffu, idx, r * 8);

    // ---- gather: 4 rows x 4 float4 per lane; all loads before all stores ----
    float4 buf[ROWS_PER_WARP * 4];
    #pragma unroll
    for (int r = 0; r < ROWS_PER_WARP; r++) {
        const float4* __restrict__ src = reinterpret_cast<const float4*>(
            inputs + (size_t)(row0 + r) * 4096 + (size_t)idxs[r] * 512);
        #pragma unroll
        for (int i = 0; i < 4; i++)
            buf[r * 4 + i] = __ldcs(src + lane + i * 32);
    }

    #pragma unroll
    for (int r = 0; r < ROWS_PER_WARP; r++) {
        float4* __restrict__ dst =
            reinterpret_cast<float4*>(out + (size_t)(row0 + r) * 512);
        #pragma unroll
        for (int i = 0; i < 4; i++)
            __stcs(dst + lane + i * 32, buf[r * 4 + i]);
    }
}

extern "C" void kernel_launch(void* const* d_in, const int* in_sizes, int n_in,
                              void* d_out, int out_size) {
    const float* inputs  = (const float*)d_in[0];
    const float* routing = (const float*)d_in[1];
    float* out = (float*)d_out;

    const int B = in_sizes[1] / 8;  // routing_inputs has B*8 elements
    const int blocks = (B + ROWS_PER_BLOCK - 1) / ROWS_PER_BLOCK;  // 512

    dense_routing_mask_kernel<<<blocks, 256>>>(inputs, routing, out, B);
}